// round 10
// baseline (speedup 1.0000x reference)
#include <cuda_runtime.h>

// Problem dims (fixed by the reference)
#define Bn  4
#define Qn  256
#define KVn 1024
#define Hn  128
#define VSn 256

// Scratch (no cudaMalloc allowed)
__device__ float g_Eq[Bn * Qn * Hn];    // e^{2*clamp(q_proj)}
__device__ float g_Ek[Bn * KVn * Hn];   // e^{2*clamp(k_proj)}

// 2*log2(e): e^{2x} = 2^{x * 2*log2(e)}
#define TWO_LOG2E 2.885390081777927f

// ---------------------------------------------------------------------------
// Kernel 1: project rows, emit E = exp2(clamp(proj, +-40) * 2*log2(e)).
// 256 threads: row-group rg = t>>7 (4 rows each), column = t&127.
// Key rows >= valid_len are skipped entirely (never read downstream).
// ---------------------------------------------------------------------------
__global__ __launch_bounds__(256)
void proj_kernel(const float* __restrict__ queries,
                 const float* __restrict__ keys,
                 const float* __restrict__ Wq,
                 const float* __restrict__ Wk,
                 const int* __restrict__ valid_lens) {
    const int r0 = blockIdx.x * 8;
    const float* in;
    const float* W;
    float* outp;
    if (r0 < Bn * Qn) {
        in   = queries + r0 * Hn;
        W    = Wq;
        outp = g_Eq + r0 * Hn;
    } else {
        const int rr = r0 - Bn * Qn;          // global key row
        const int b  = rr >> 10;              // / KVn
        const int j0 = rr & (KVn - 1);
        if (j0 >= valid_lens[b]) return;      // these Ek rows are never read
        in   = keys + rr * Hn;
        W    = Wk;
        outp = g_Ek + rr * Hn;
    }
    __shared__ float s[8][Hn];
    const int t = threadIdx.x;
    #pragma unroll
    for (int u = 0; u < 4; u++) {
        const int idx = t + u * 256;
        s[idx >> 7][idx & 127] = in[idx];
    }
    __syncthreads();

    const int rg  = t >> 7;        // row group: rows rg*4 .. rg*4+3
    const int col = t & 127;

    float a[4];
    #pragma unroll
    for (int r = 0; r < 4; r++) a[r] = 0.f;

    #pragma unroll 8
    for (int kk = 0; kk < Hn; kk++) {
        const float w = W[kk * Hn + col];
        #pragma unroll
        for (int r = 0; r < 4; r++)
            a[r] = fmaf(s[rg * 4 + r][kk], w, a[r]);
    }
    #pragma unroll
    for (int r = 0; r < 4; r++) {
        float p = fminf(fmaxf(a[r], -40.f), 40.f) * TWO_LOG2E;
        float e;
        asm("ex2.approx.f32 %0, %1;" : "=f"(e) : "f"(p));
        outp[(rg * 4 + r) * Hn + col] = e;
    }
}

// ---------------------------------------------------------------------------
// Kernel 2 (fused): one block per query PAIR. 256 threads, 4 blocks/SM ->
// grid 512 = one wave. Batch-interleaved so each SM gets mixed valid_lens.
//
// Pass 1 (scores): 16-lane-per-key, 2 keys/warp, both queries per key load.
//   tanh(x) = 1 - 2/(Eq*Ek + 1); Sum_h w_h hoisted into accumulator init.
//   MUFU halved by pairing: w0/d0 + w1/d1 = (w0*d1c + w1*d0c)*rcp(d0c*d1c),
//   d clamped at 1e18 (true term < 3e-18 there, so the clamp is exact-enough
//   and keeps all products finite -> no inf*0).
// Pass 2: per-row block softmax matching the -1e6 masking semantics;
//   valid_len == 0 degenerates to uniform weights over all KV.
//   RACE-FREE: max and sum use SEPARATE smem arrays with barriers between
//   phases (a shared array reused for max then sum lets a delayed warp read
//   another warp's sum as its max -> per-warp-inconsistent M -> wrong output).
// Pass 3: AV, thread-per-column, each V element feeds both query rows.
// ---------------------------------------------------------------------------
__global__ __launch_bounds__(256, 4)
void attn_kernel(const float* __restrict__ values,
                 const int* __restrict__ valid_lens,
                 const float* __restrict__ wv,
                 float* __restrict__ out) {
    const int pair = blockIdx.x;            // [0, 512)
    const int b    = pair & 3;              // batch-interleaved
    const int qp   = pair >> 2;             // [0, 128)
    const int row0 = (b << 8) + (qp << 1);
    const int row1 = row0 + 1;
    const int tid  = threadIdx.x;
    const int lane = tid & 31;
    const int warp = tid >> 5;

    __shared__ float s_sc[2][KVn];
    __shared__ float s_rmax[2][8];
    __shared__ float s_rsum[2][8];

    const int L     = valid_lens[b];
    const bool uni  = (L <= 0);
    const int effL  = uni ? KVn : L;

    float Z0, Z1;
    if (!uni) {
        // ---- Pass 1: scores for both query rows ----
        const int sub = lane >> 4;          // which key of the duo (0..1)
        const int hb  = (lane & 15) << 3;   // h-chunk base (8 floats)

        float4 qa[2], qb[2], w2[2];
        float wsum_l = 0.f;
        #pragma unroll
        for (int i = 0; i < 2; i++) {
            qa[i] = *reinterpret_cast<const float4*>(&g_Eq[row0 * Hn + hb + i * 4]);
            qb[i] = *reinterpret_cast<const float4*>(&g_Eq[row1 * Hn + hb + i * 4]);
            float4 w = *reinterpret_cast<const float4*>(&wv[hb + i * 4]);
            wsum_l += ((w.x + w.y) + (w.z + w.w));
            w2[i] = make_float4(-2.f * w.x, -2.f * w.y, -2.f * w.z, -2.f * w.w);
        }
        const float* kbp = g_Ek + b * KVn * Hn;

        for (int j0 = warp * 2; j0 < effL; j0 += 16) {
            const int key = j0 + sub;
            const int kc  = (key < effL) ? key : (effL - 1);   // safe load

            float4 k4[2];
            #pragma unroll
            for (int i = 0; i < 2; i++)
                k4[i] = *reinterpret_cast<const float4*>(&kbp[kc * Hn + hb + i * 4]);

            float sa0 = wsum_l, sb0 = 0.f, sa1 = wsum_l, sb1 = 0.f;
            #pragma unroll
            for (int i = 0; i < 2; i++) {
                // query row0
                float d0 = fminf(fmaf(qa[i].x, k4[i].x, 1.f), 1e18f);
                float d1 = fminf(fmaf(qa[i].y, k4[i].y, 1.f), 1e18f);
                float d2 = fminf(fmaf(qa[i].z, k4[i].z, 1.f), 1e18f);
                float d3 = fminf(fmaf(qa[i].w, k4[i].w, 1.f), 1e18f);
                float n01 = fmaf(w2[i].x, d1, w2[i].y * d0);
                float n23 = fmaf(w2[i].z, d3, w2[i].w * d2);
                float r01, r23;
                asm("rcp.approx.f32 %0, %1;" : "=f"(r01) : "f"(d0 * d1));
                asm("rcp.approx.f32 %0, %1;" : "=f"(r23) : "f"(d2 * d3));
                sa0 = fmaf(n01, r01, sa0);
                sb0 = fmaf(n23, r23, sb0);
                // query row1
                float e0 = fminf(fmaf(qb[i].x, k4[i].x, 1.f), 1e18f);
                float e1 = fminf(fmaf(qb[i].y, k4[i].y, 1.f), 1e18f);
                float e2 = fminf(fmaf(qb[i].z, k4[i].z, 1.f), 1e18f);
                float e3 = fminf(fmaf(qb[i].w, k4[i].w, 1.f), 1e18f);
                float m01 = fmaf(w2[i].x, e1, w2[i].y * e0);
                float m23 = fmaf(w2[i].z, e3, w2[i].w * e2);
                float u01, u23;
                asm("rcp.approx.f32 %0, %1;" : "=f"(u01) : "f"(e0 * e1));
                asm("rcp.approx.f32 %0, %1;" : "=f"(u23) : "f"(e2 * e3));
                sa1 = fmaf(m01, u01, sa1);
                sb1 = fmaf(m23, u23, sb1);
            }
            float s = sa0 + sb0;
            float t = sa1 + sb1;

            // reduce across the 16 lanes of each key group (both keys at once)
            s += __shfl_xor_sync(0xffffffffu, s, 1);
            t += __shfl_xor_sync(0xffffffffu, t, 1);
            s += __shfl_xor_sync(0xffffffffu, s, 2);
            t += __shfl_xor_sync(0xffffffffu, t, 2);
            s += __shfl_xor_sync(0xffffffffu, s, 4);
            t += __shfl_xor_sync(0xffffffffu, t, 4);
            s += __shfl_xor_sync(0xffffffffu, s, 8);
            t += __shfl_xor_sync(0xffffffffu, t, 8);

            if ((lane & 15) == 0 && key < effL) {
                s_sc[0][key] = s;
                s_sc[1][key] = t;
            }
        }
        __syncthreads();

        // ---- Pass 2a: per-row block max (writes s_rmax only) ----
        #pragma unroll
        for (int r = 0; r < 2; r++) {
            float m = -3.0e38f;
            for (int jj = tid; jj < effL; jj += 256) m = fmaxf(m, s_sc[r][jj]);
            #pragma unroll
            for (int o = 16; o > 0; o >>= 1)
                m = fmaxf(m, __shfl_xor_sync(0xffffffffu, m, o));
            if (lane == 0) s_rmax[r][warp] = m;
        }
        __syncthreads();

        // ---- Pass 2b: exp + sum (reads s_rmax, writes s_rsum: no aliasing) ----
        #pragma unroll
        for (int r = 0; r < 2; r++) {
            float M = s_rmax[r][0];
            #pragma unroll
            for (int k = 1; k < 8; k++) M = fmaxf(M, s_rmax[r][k]);

            float z = 0.f;
            for (int jj = tid; jj < effL; jj += 256) {
                const float e = __expf(s_sc[r][jj] - M);
                s_sc[r][jj] = e;
                z += e;
            }
            #pragma unroll
            for (int o = 16; o > 0; o >>= 1)
                z += __shfl_xor_sync(0xffffffffu, z, o);
            if (lane == 0) s_rsum[r][warp] = z;
        }
        __syncthreads();
        Z0 = s_rsum[0][0]; Z1 = s_rsum[1][0];
        #pragma unroll
        for (int k = 1; k < 8; k++) {
            Z0 += s_rsum[0][k];
            Z1 += s_rsum[1][k];
        }
    } else {
        // valid_len == 0: reference gives softmax over all -1e6 -> uniform
        for (int jj = tid; jj < KVn; jj += 256) {
            s_sc[0][jj] = 1.0f;
            s_sc[1][jj] = 1.0f;
        }
        __syncthreads();
        Z0 = (float)KVn;
        Z1 = (float)KVn;
    }

    // ---- Pass 3: AV. Thread tid owns column tid; V feeds both rows ----
    const int c = tid;
    const float* vb = values + (size_t)b * KVn * VSn + c;
    float a0[4], a1[4];
    #pragma unroll
    for (int u = 0; u < 4; u++) { a0[u] = 0.f; a1[u] = 0.f; }

    int j = 0;
    for (; j + 4 <= effL; j += 4) {
        #pragma unroll
        for (int u = 0; u < 4; u++) {
            const float v = vb[(j + u) * VSn];
            a0[u] = fmaf(s_sc[0][j + u], v, a0[u]);
            a1[u] = fmaf(s_sc[1][j + u], v, a1[u]);
        }
    }
    for (; j < effL; j++) {
        const float v = vb[j * VSn];
        a0[0] = fmaf(s_sc[0][j], v, a0[0]);
        a1[0] = fmaf(s_sc[1][j], v, a1[0]);
    }

    out[row0 * VSn + c] = ((a0[0] + a0[1]) + (a0[2] + a0[3])) / Z0;
    out[row1 * VSn + c] = ((a1[0] + a1[1]) + (a1[2] + a1[3])) / Z1;
}

// ---------------------------------------------------------------------------
extern "C" void kernel_launch(void* const* d_in, const int* in_sizes, int n_in,
                              void* d_out, int out_size) {
    const float* queries = (const float*)d_in[0];
    const float* keys    = (const float*)d_in[1];
    const float* values  = (const float*)d_in[2];
    const int*   valid   = (const int*)d_in[3];
    const float* Wq      = (const float*)d_in[4];
    const float* Wk      = (const float*)d_in[5];
    const float* wv      = (const float*)d_in[6];
    float* out           = (float*)d_out;

    proj_kernel<<<(Bn * Qn + Bn * KVn) / 8, 256>>>(queries, keys, Wq, Wk, valid);
    attn_kernel<<<(Bn * Qn) / 2, 256>>>(values, valid, wv, out);
}

// round 11
// speedup vs baseline: 1.1921x; 1.1921x over previous
#include <cuda_runtime.h>

// Problem dims (fixed by the reference)
#define Bn  4
#define Qn  256
#define KVn 1024
#define Hn  128
#define VSn 256

// Scratch (no cudaMalloc allowed)
__device__ float g_Eq[Bn * Qn * Hn];    // e^{2*clamp(q_proj)}
__device__ float g_Ek[Bn * KVn * Hn];   // e^{2*clamp(k_proj)}

// 2*log2(e): e^{2x} = 2^{x * 2*log2(e)}
#define TWO_LOG2E 2.885390081777927f

// ---------------------------------------------------------------------------
// Kernel 1: project rows, emit E = exp2(clamp(proj, +-40) * 2*log2(e)).
// 256 threads: row-group rg = t>>7 (4 rows each), column = t&127.
// Key rows >= valid_len are skipped entirely (never read downstream).
// ---------------------------------------------------------------------------
__global__ __launch_bounds__(256)
void proj_kernel(const float* __restrict__ queries,
                 const float* __restrict__ keys,
                 const float* __restrict__ Wq,
                 const float* __restrict__ Wk,
                 const int* __restrict__ valid_lens) {
    const int r0 = blockIdx.x * 8;
    const float* in;
    const float* W;
    float* outp;
    if (r0 < Bn * Qn) {
        in   = queries + r0 * Hn;
        W    = Wq;
        outp = g_Eq + r0 * Hn;
    } else {
        const int rr = r0 - Bn * Qn;          // global key row
        const int b  = rr >> 10;              // / KVn
        const int j0 = rr & (KVn - 1);
        if (j0 >= valid_lens[b]) return;      // these Ek rows are never read
        in   = keys + rr * Hn;
        W    = Wk;
        outp = g_Ek + rr * Hn;
    }
    __shared__ float s[8][Hn];
    const int t = threadIdx.x;
    #pragma unroll
    for (int u = 0; u < 4; u++) {
        const int idx = t + u * 256;
        s[idx >> 7][idx & 127] = in[idx];
    }
    __syncthreads();

    const int rg  = t >> 7;        // row group: rows rg*4 .. rg*4+3
    const int col = t & 127;

    float a[4];
    #pragma unroll
    for (int r = 0; r < 4; r++) a[r] = 0.f;

    #pragma unroll 8
    for (int kk = 0; kk < Hn; kk++) {
        const float w = W[kk * Hn + col];
        #pragma unroll
        for (int r = 0; r < 4; r++)
            a[r] = fmaf(s[rg * 4 + r][kk], w, a[r]);
    }
    #pragma unroll
    for (int r = 0; r < 4; r++) {
        float p = fminf(fmaxf(a[r], -40.f), 40.f) * TWO_LOG2E;
        float e;
        asm("ex2.approx.f32 %0, %1;" : "=f"(e) : "f"(p));
        outp[(rg * 4 + r) * Hn + col] = e;
    }
}

// ---------------------------------------------------------------------------
// Kernel 2 (fused): one block per query PAIR. 256 threads, 4 blocks/SM.
// Batch map b = (pair + (pair>>2)) & 3: bijective, and blocks that share an
// SM (bid stride 148 ≡ 0 mod 4 -> delta(b) = 148+37 ≡ 1 mod 4) cycle through
// all batches, balancing unequal valid_lens per SM.
//
// Pass 1 (scores): 16-lane-per-key, 2 keys/warp, both queries per key load.
//   tanh(x) = 1 - 2/(Eq*Ek + 1); Sum_h w_h hoisted into accumulator init.
//   MUFU halved by pairing: w0/d0 + w1/d1 = (w0*d1c + w1*d0c)*rcp(d0c*d1c),
//   d clamped at 1e18 (true term < 3e-18 there, so the clamp is exact-enough
//   and keeps all products finite -> no inf*0).
// Pass 2: per-row block softmax, race-free (separate max/sum scratch),
//   matching the -1e6 masking semantics; valid_len==0 -> uniform over all KV.
// Pass 3: AV with LDG.128: thread owns 4 columns (c4=(tid&63)*4) and one of
//   4 j-residues (joff=tid>>6); partials combined through smem. 4x fewer
//   load instructions than scalar (the old LSU-issue floor ~14us).
// ---------------------------------------------------------------------------
__global__ __launch_bounds__(256, 4)
void attn_kernel(const float* __restrict__ values,
                 const int* __restrict__ valid_lens,
                 const float* __restrict__ wv,
                 float* __restrict__ out) {
    const int pair = blockIdx.x;                 // [0, 512)
    const int qp   = pair >> 2;                  // [0, 128)
    const int b    = (pair + qp) & 3;            // SM-cycling batch mix
    const int row0 = (b << 8) + (qp << 1);
    const int row1 = row0 + 1;
    const int tid  = threadIdx.x;
    const int lane = tid & 31;
    const int warp = tid >> 5;

    __shared__ float s_sc[2][KVn];
    __shared__ float s_av[2][4][VSn];
    __shared__ float s_rmax[2][8];
    __shared__ float s_rsum[2][8];

    const int L     = valid_lens[b];
    const bool uni  = (L <= 0);
    const int effL  = uni ? KVn : L;

    float Z0, Z1;
    if (!uni) {
        // ---- Pass 1: scores for both query rows ----
        const int sub = lane >> 4;          // which key of the duo (0..1)
        const int hb  = (lane & 15) << 3;   // h-chunk base (8 floats)

        float4 qa[2], qb[2], w2[2];
        float wsum_l = 0.f;
        #pragma unroll
        for (int i = 0; i < 2; i++) {
            qa[i] = *reinterpret_cast<const float4*>(&g_Eq[row0 * Hn + hb + i * 4]);
            qb[i] = *reinterpret_cast<const float4*>(&g_Eq[row1 * Hn + hb + i * 4]);
            float4 w = *reinterpret_cast<const float4*>(&wv[hb + i * 4]);
            wsum_l += ((w.x + w.y) + (w.z + w.w));
            w2[i] = make_float4(-2.f * w.x, -2.f * w.y, -2.f * w.z, -2.f * w.w);
        }
        const float* kbp = g_Ek + b * KVn * Hn;

        for (int j0 = warp * 2; j0 < effL; j0 += 16) {
            const int key = j0 + sub;
            const int kc  = (key < effL) ? key : (effL - 1);   // safe load

            float4 k4[2];
            #pragma unroll
            for (int i = 0; i < 2; i++)
                k4[i] = *reinterpret_cast<const float4*>(&kbp[kc * Hn + hb + i * 4]);

            float sa0 = wsum_l, sb0 = 0.f, sa1 = wsum_l, sb1 = 0.f;
            #pragma unroll
            for (int i = 0; i < 2; i++) {
                // query row0
                float d0 = fminf(fmaf(qa[i].x, k4[i].x, 1.f), 1e18f);
                float d1 = fminf(fmaf(qa[i].y, k4[i].y, 1.f), 1e18f);
                float d2 = fminf(fmaf(qa[i].z, k4[i].z, 1.f), 1e18f);
                float d3 = fminf(fmaf(qa[i].w, k4[i].w, 1.f), 1e18f);
                float n01 = fmaf(w2[i].x, d1, w2[i].y * d0);
                float n23 = fmaf(w2[i].z, d3, w2[i].w * d2);
                float r01, r23;
                asm("rcp.approx.f32 %0, %1;" : "=f"(r01) : "f"(d0 * d1));
                asm("rcp.approx.f32 %0, %1;" : "=f"(r23) : "f"(d2 * d3));
                sa0 = fmaf(n01, r01, sa0);
                sb0 = fmaf(n23, r23, sb0);
                // query row1
                float e0 = fminf(fmaf(qb[i].x, k4[i].x, 1.f), 1e18f);
                float e1 = fminf(fmaf(qb[i].y, k4[i].y, 1.f), 1e18f);
                float e2 = fminf(fmaf(qb[i].z, k4[i].z, 1.f), 1e18f);
                float e3 = fminf(fmaf(qb[i].w, k4[i].w, 1.f), 1e18f);
                float m01 = fmaf(w2[i].x, e1, w2[i].y * e0);
                float m23 = fmaf(w2[i].z, e3, w2[i].w * e2);
                float u01, u23;
                asm("rcp.approx.f32 %0, %1;" : "=f"(u01) : "f"(e0 * e1));
                asm("rcp.approx.f32 %0, %1;" : "=f"(u23) : "f"(e2 * e3));
                sa1 = fmaf(m01, u01, sa1);
                sb1 = fmaf(m23, u23, sb1);
            }
            float s = sa0 + sb0;
            float t = sa1 + sb1;

            // reduce across the 16 lanes of each key group (both keys at once)
            s += __shfl_xor_sync(0xffffffffu, s, 1);
            t += __shfl_xor_sync(0xffffffffu, t, 1);
            s += __shfl_xor_sync(0xffffffffu, s, 2);
            t += __shfl_xor_sync(0xffffffffu, t, 2);
            s += __shfl_xor_sync(0xffffffffu, s, 4);
            t += __shfl_xor_sync(0xffffffffu, t, 4);
            s += __shfl_xor_sync(0xffffffffu, s, 8);
            t += __shfl_xor_sync(0xffffffffu, t, 8);

            if ((lane & 15) == 0 && key < effL) {
                s_sc[0][key] = s;
                s_sc[1][key] = t;
            }
        }
        __syncthreads();

        // ---- Pass 2a: per-row block max (writes s_rmax only) ----
        #pragma unroll
        for (int r = 0; r < 2; r++) {
            float m = -3.0e38f;
            for (int jj = tid; jj < effL; jj += 256) m = fmaxf(m, s_sc[r][jj]);
            #pragma unroll
            for (int o = 16; o > 0; o >>= 1)
                m = fmaxf(m, __shfl_xor_sync(0xffffffffu, m, o));
            if (lane == 0) s_rmax[r][warp] = m;
        }
        __syncthreads();

        // ---- Pass 2b: exp + sum (reads s_rmax, writes s_rsum: no aliasing) ----
        #pragma unroll
        for (int r = 0; r < 2; r++) {
            float M = s_rmax[r][0];
            #pragma unroll
            for (int k = 1; k < 8; k++) M = fmaxf(M, s_rmax[r][k]);

            float z = 0.f;
            for (int jj = tid; jj < effL; jj += 256) {
                const float e = __expf(s_sc[r][jj] - M);
                s_sc[r][jj] = e;
                z += e;
            }
            #pragma unroll
            for (int o = 16; o > 0; o >>= 1)
                z += __shfl_xor_sync(0xffffffffu, z, o);
            if (lane == 0) s_rsum[r][warp] = z;
        }
        __syncthreads();
        Z0 = s_rsum[0][0]; Z1 = s_rsum[1][0];
        #pragma unroll
        for (int k = 1; k < 8; k++) {
            Z0 += s_rsum[0][k];
            Z1 += s_rsum[1][k];
        }
    } else {
        // valid_len == 0: reference gives softmax over all -1e6 -> uniform
        for (int jj = tid; jj < KVn; jj += 256) {
            s_sc[0][jj] = 1.0f;
            s_sc[1][jj] = 1.0f;
        }
        __syncthreads();
        Z0 = (float)KVn;
        Z1 = (float)KVn;
    }

    // ---- Pass 3: AV with LDG.128 ----
    // Thread owns cols [c4, c4+4) and j-residue joff; each V row segment is
    // loaded once per block as a float4 and feeds both query rows.
    const int c4   = (tid & 63) << 2;
    const int joff = tid >> 6;
    const float* vrow = values + (size_t)b * KVn * VSn + c4;

    float a0x = 0.f, a0y = 0.f, a0z = 0.f, a0w = 0.f;
    float a1x = 0.f, a1y = 0.f, a1z = 0.f, a1w = 0.f;
    #pragma unroll 4
    for (int j = joff; j < effL; j += 4) {
        const float4 v = *reinterpret_cast<const float4*>(vrow + (size_t)j * VSn);
        const float p0 = s_sc[0][j];
        const float p1 = s_sc[1][j];
        a0x = fmaf(p0, v.x, a0x);  a1x = fmaf(p1, v.x, a1x);
        a0y = fmaf(p0, v.y, a0y);  a1y = fmaf(p1, v.y, a1y);
        a0z = fmaf(p0, v.z, a0z);  a1z = fmaf(p1, v.z, a1z);
        a0w = fmaf(p0, v.w, a0w);  a1w = fmaf(p1, v.w, a1w);
    }
    *reinterpret_cast<float4*>(&s_av[0][joff][c4]) = make_float4(a0x, a0y, a0z, a0w);
    *reinterpret_cast<float4*>(&s_av[1][joff][c4]) = make_float4(a1x, a1y, a1z, a1w);
    __syncthreads();

    // combine the 4 j-residue partials; threads 0..255 each own one column
    {
        const int c = tid;
        const float o0 = (s_av[0][0][c] + s_av[0][1][c]) +
                         (s_av[0][2][c] + s_av[0][3][c]);
        const float o1 = (s_av[1][0][c] + s_av[1][1][c]) +
                         (s_av[1][2][c] + s_av[1][3][c]);
        out[row0 * VSn + c] = o0 / Z0;
        out[row1 * VSn + c] = o1 / Z1;
    }
}

// ---------------------------------------------------------------------------
extern "C" void kernel_launch(void* const* d_in, const int* in_sizes, int n_in,
                              void* d_out, int out_size) {
    const float* queries = (const float*)d_in[0];
    const float* keys    = (const float*)d_in[1];
    const float* values  = (const float*)d_in[2];
    const int*   valid   = (const int*)d_in[3];
    const float* Wq      = (const float*)d_in[4];
    const float* Wk      = (const float*)d_in[5];
    const float* wv      = (const float*)d_in[6];
    float* out           = (float*)d_out;

    proj_kernel<<<(Bn * Qn + Bn * KVn) / 8, 256>>>(queries, keys, Wq, Wk, valid);
    attn_kernel<<<(Bn * Qn) / 2, 256>>>(values, valid, wv, out);
}